// round 6
// baseline (speedup 1.0000x reference)
#include <cuda_runtime.h>
#include <cstdint>

// Problem shape (fixed for this bench instance)
#define BB 1024
#define LL 512
#define TT 64

// Scratch for gold scores (allocation-free: __device__ global)
__device__ float g_gold[BB];

// ---------------------------------------------------------------------------
// Kernel 1: gold path score.  One warp per batch row.
// NOTE: tags is int32 (JAX x64 disabled downcasts jnp.int64 -> int32).
// ---------------------------------------------------------------------------
__global__ void gold_kernel(const float* __restrict__ logits,
                            const int* __restrict__ tags,
                            const int* __restrict__ mask,
                            const float* __restrict__ trans)
{
    int gw   = (blockIdx.x * blockDim.x + threadIdx.x) >> 5;
    int lane = threadIdx.x & 31;
    if (gw >= BB) return;

    const int*   tg = tags   + (size_t)gw * LL;
    const int*   mk = mask   + (size_t)gw * LL;
    const float* lg = logits + (size_t)gw * LL * TT;

    float acc = 0.f;
    for (int p = lane; p < LL; p += 32) {
        int   t0 = tg[p];
        float m0 = (mk[p] > 0) ? 1.f : 0.f;
        acc += lg[p * TT + t0] * m0;
        if (p + 1 < LL) {
            int   t1 = tg[p + 1];
            float m1 = (mk[p + 1] > 0) ? 1.f : 0.f;
            acc += trans[t0 * TT + t1] * m1;
        }
    }
    #pragma unroll
    for (int o = 16; o; o >>= 1) acc += __shfl_xor_sync(0xffffffffu, acc, o);
    if (lane == 0) g_gold[gw] = acc;
}

// ---------------------------------------------------------------------------
// Kernel 2: forward recursion in scaled linear space + final output.
// One warp per batch row; 7 rows per CTA; 148 CTAs cover 1024 rows.
// Lane owns columns j=lane and j+32.  exp(trans) columns live in registers.
// Invariant: alpha[b,j] = s + ln(u_j), with per-step renorm by row max m.
// ---------------------------------------------------------------------------
__global__ __launch_bounds__(224, 1)
void crf_fwd_kernel(const float* __restrict__ logits,
                    const int* __restrict__ mask,
                    const float* __restrict__ trans,
                    float* __restrict__ out)
{
    __shared__ float buf[2][7][TT];   // double-buffered alpha (linear, unscaled)

    int r    = threadIdx.x >> 5;      // warp index in block = row index in block
    int lane = threadIdx.x & 31;

    int nb = blockIdx.x;
    int b0, nrows;
    if (nb < 136) { b0 = nb * 7;                 nrows = 7; }
    else          { b0 = 136 * 7 + (nb - 136) * 6; nrows = 6; }
    if (r >= nrows) return;           // whole-warp exit; no block syncs used
    int b = b0 + r;

    // Persistent register copy of M = exp(trans) columns (lane, lane+32)
    float M0[TT], M1[TT];
    #pragma unroll
    for (int k = 0; k < TT; k++) {
        M0[k] = __expf(trans[k * TT + lane]);
        M1[k] = __expf(trans[k * TT + lane + 32]);
    }

    const float* lg = logits + (size_t)b * (LL * TT);
    const int*   mp = mask   + (size_t)b * LL;

    // ---- init at l = 0: alpha0 = emit0 (unconditional, matching reference) --
    float uA = __expf(lg[lane]);
    float uB = __expf(lg[lane + 32]);
    float m  = fmaxf(uA, uB);
    #pragma unroll
    for (int o = 16; o; o >>= 1) m = fmaxf(m, __shfl_xor_sync(0xffffffffu, m, o));

    int cur = 0;
    buf[0][r][lane]      = uA;
    buf[0][r][lane + 32] = uB;
    __syncwarp();
    float s = 0.f;

    // ---- 2-deep emission / mask prefetch ----
    float eA1 = lg[TT + lane],       eB1 = lg[TT + lane + 32];
    int   mk1 = mp[1];
    float eA2 = lg[2 * TT + lane],   eB2 = lg[2 * TT + lane + 32];
    int   mk2 = mp[2];

    for (int l = 1; l < LL; l++) {
        float eA = eA1, eB = eB1; int mk = mk1;
        eA1 = eA2; eB1 = eB2; mk1 = mk2;
        if (l + 2 < LL) {
            eA2 = __ldg(&lg[(size_t)(l + 2) * TT + lane]);
            eB2 = __ldg(&lg[(size_t)(l + 2) * TT + lane + 32]);
            mk2 = __ldg(&mp[l + 2]);
        }

        // dot_j = sum_k u_k * M[k][j]  (8 independent FFMA chains)
        float d0 = 0.f, d1 = 0.f, d2 = 0.f, d3 = 0.f;
        float f0 = 0.f, f1 = 0.f, f2 = 0.f, f3 = 0.f;
        const float4* uv = (const float4*)buf[cur][r];
        #pragma unroll
        for (int k4 = 0; k4 < 16; k4++) {
            float4 u4 = uv[k4];          // broadcast LDS.128 (same addr warp-wide)
            int k = 4 * k4;
            d0 = fmaf(u4.x, M0[k + 0], d0);
            d1 = fmaf(u4.y, M0[k + 1], d1);
            d2 = fmaf(u4.z, M0[k + 2], d2);
            d3 = fmaf(u4.w, M0[k + 3], d3);
            f0 = fmaf(u4.x, M1[k + 0], f0);
            f1 = fmaf(u4.y, M1[k + 1], f1);
            f2 = fmaf(u4.z, M1[k + 2], f2);
            f3 = fmaf(u4.w, M1[k + 3], f3);
        }
        float dotA = (d0 + d1) + (d2 + d3);
        float dotB = (f0 + f1) + (f2 + f3);

        if (mk > 0) {                      // warp-uniform branch
            float invm = __fdividef(1.0f, m);
            uA = dotA * invm * __expf(eA);
            uB = dotB * invm * __expf(eB);
            s += __logf(m);
        }
        // (mask==0: u, s unchanged — alpha carried forward)

        // new row max (pending scale for next step)
        m = fmaxf(uA, uB);
        #pragma unroll
        for (int o = 16; o; o >>= 1) m = fmaxf(m, __shfl_xor_sync(0xffffffffu, m, o));

        int nxt = cur ^ 1;
        buf[nxt][r][lane]      = uA;
        buf[nxt][r][lane + 32] = uB;
        __syncwarp();
        cur = nxt;
    }

    // logZ = s + ln(sum_j u_j);  out = logZ - gold
    float tot = uA + uB;
    #pragma unroll
    for (int o = 16; o; o >>= 1) tot += __shfl_xor_sync(0xffffffffu, tot, o);
    if (lane == 0) out[b] = s + __logf(tot) - g_gold[b];
}

// ---------------------------------------------------------------------------
// Launch: gold first, then forward (same stream -> ordered in the graph).
// ---------------------------------------------------------------------------
extern "C" void kernel_launch(void* const* d_in, const int* in_sizes, int n_in,
                              void* d_out, int out_size)
{
    const float* logits = (const float*)d_in[0];
    const int*   tags   = (const int*)d_in[1];
    const int*   mask   = (const int*)d_in[2];
    const float* trans  = (const float*)d_in[3];
    float*       out    = (float*)d_out;

    gold_kernel<<<BB / 8, 256>>>(logits, tags, mask, trans);
    crf_fwd_kernel<<<148, 224>>>(logits, mask, trans, out);
}

// round 9
// speedup vs baseline: 1.3847x; 1.3847x over previous
#include <cuda_runtime.h>
#include <cstdint>

#define BB 1024
#define LL 512
#define TT 64

typedef unsigned long long ull;

// ---- packed f32x2 helpers (sm_103a; ptxas never emits these from C++) ----
__device__ __forceinline__ ull packf2(float lo, float hi) {
    ull r; asm("mov.b64 %0, {%1, %2};" : "=l"(r) : "f"(lo), "f"(hi)); return r;
}
__device__ __forceinline__ void unpackf2(ull v, float& lo, float& hi) {
    asm("mov.b64 {%0, %1}, %2;" : "=f"(lo), "=f"(hi) : "l"(v));
}
__device__ __forceinline__ ull fma2(ull a, ull b, ull c) {
    ull d; asm("fma.rn.f32x2 %0, %1, %2, %3;" : "=l"(d) : "l"(a), "l"(b), "l"(c)); return d;
}
__device__ __forceinline__ ull add2(ull a, ull b) {
    ull d; asm("add.rn.f32x2 %0, %1, %2;" : "=l"(d) : "l"(a), "l"(b)); return d;
}

// ---------------------------------------------------------------------------
// Single fused kernel: gold score + forward recursion in scaled linear space.
// One warp per batch row; 7 rows/CTA; 148 CTAs (one wave, 136x7 + 12x6).
// Lane owns ADJACENT columns j0=2*lane, j1=2*lane+1 so SMEM u-pairs alias
// directly to f32x2 operands. exp(trans) lives prepacked in registers.
// Invariant: alpha[b,j] = s + ln(u_j); renorm by warp max every 4 steps.
// ---------------------------------------------------------------------------
__global__ __launch_bounds__(224, 1)
void crf_kernel(const float* __restrict__ logits,
                const int* __restrict__ tags,
                const int* __restrict__ mask,
                const float* __restrict__ trans,
                float* __restrict__ out)
{
    __shared__ __align__(16) float buf[2][7][TT];   // double-buffered alpha (linear)

    int r    = threadIdx.x >> 5;
    int lane = threadIdx.x & 31;

    int nb = blockIdx.x, b0, nrows;
    if (nb < 136) { b0 = nb * 7;              nrows = 7; }
    else          { b0 = 952 + (nb - 136) * 6; nrows = 6; }
    if (r >= nrows) return;                   // whole-warp exit; no block syncs
    int b = b0 + r;

    const float* lg = logits + (size_t)b * (LL * TT);
    const int*   mp = mask   + (size_t)b * LL;
    const int*   tg = tags   + (size_t)b * LL;

    // ---- gold path score (overlaps with M setup below) --------------------
    float gacc = 0.f;
    #pragma unroll 4
    for (int p = lane; p < LL; p += 32) {
        int   t0 = tg[p];
        float m0 = (mp[p] > 0) ? 1.f : 0.f;
        gacc += lg[p * TT + t0] * m0;
        if (p + 1 < LL) {
            int   t1 = tg[p + 1];
            float m1 = (mp[p + 1] > 0) ? 1.f : 0.f;
            gacc += trans[t0 * TT + t1] * m1;
        }
    }
    #pragma unroll
    for (int o = 16; o; o >>= 1) gacc += __shfl_xor_sync(0xffffffffu, gacc, o);

    // ---- prepacked M = exp(trans): pair over k, per owned column ----------
    int j0 = 2 * lane, j1 = 2 * lane + 1;
    ull MA[32], MB[32];
    #pragma unroll
    for (int p = 0; p < 32; p++) {
        MA[p] = packf2(__expf(trans[(2 * p) * TT + j0]), __expf(trans[(2 * p + 1) * TT + j0]));
        MB[p] = packf2(__expf(trans[(2 * p) * TT + j1]), __expf(trans[(2 * p + 1) * TT + j1]));
    }

    // ---- init l=0: alpha0 = emit0 ----------------------------------------
    const float2* lg2 = (const float2*)lg;    // [LL][32] column pairs
    float2 ei = lg2[lane];
    float uA = __expf(ei.x), uB = __expf(ei.y);
    float s = 0.f;
    int cnt = 1;                               // applied steps since renorm
    int cur = 0;
    ((ull*)buf[0][r])[lane] = packf2(uA, uB);  // STS.64, pair-contiguous
    __syncwarp();

    // ---- 2-deep emission/mask prefetch -----------------------------------
    float2 e1 = lg2[32 + lane];  int mk1 = mp[1];
    float2 e2 = lg2[64 + lane];  int mk2 = mp[2];

    for (int l = 1; l < LL; l++) {
        float2 e = e1; int mk = mk1;
        e1 = e2; mk1 = mk2;
        if (l + 2 < LL) {
            e2  = __ldg(&lg2[(l + 2) * 32 + lane]);
            mk2 = __ldg(&mp[l + 2]);
        }

        if (mk > 0) {                          // warp-uniform branch
            float EA = __expf(e.x), EB = __expf(e.y);

            // dot_j = sum_k u_k * M[k][j], packed along k (f32x2)
            ull aA0 = 0, aA1 = 0, aA2 = 0, aA3 = 0;
            ull aB0 = 0, aB1 = 0, aB2 = 0, aB3 = 0;
            const ulonglong2* uv = (const ulonglong2*)buf[cur][r];
            #pragma unroll
            for (int i = 0; i < 16; i++) {
                ulonglong2 up = uv[i];         // broadcast LDS.128 -> 2 packed pairs
                if (i & 1) {
                    aA2 = fma2(up.x, MA[2 * i],     aA2);
                    aA3 = fma2(up.y, MA[2 * i + 1], aA3);
                    aB2 = fma2(up.x, MB[2 * i],     aB2);
                    aB3 = fma2(up.y, MB[2 * i + 1], aB3);
                } else {
                    aA0 = fma2(up.x, MA[2 * i],     aA0);
                    aA1 = fma2(up.y, MA[2 * i + 1], aA1);
                    aB0 = fma2(up.x, MB[2 * i],     aB0);
                    aB1 = fma2(up.y, MB[2 * i + 1], aB1);
                }
            }
            ull sAp = add2(add2(aA0, aA2), add2(aA1, aA3));
            ull sBp = add2(add2(aB0, aB2), add2(aB1, aB3));
            float alo, ahi, blo, bhi;
            unpackf2(sAp, alo, ahi);
            unpackf2(sBp, blo, bhi);
            uA = (alo + ahi) * EA;
            uB = (blo + bhi) * EB;

            // renorm every 4 applied steps (growth <= ~5e5/step, safe in fp32)
            if (++cnt >= 4) {
                float mm = fmaxf(uA, uB);
                #pragma unroll
                for (int o = 16; o; o >>= 1)
                    mm = fmaxf(mm, __shfl_xor_sync(0xffffffffu, mm, o));
                float inv = __fdividef(1.0f, mm);
                uA *= inv; uB *= inv;
                s += __logf(mm);
                cnt = 0;
            }

            int nxt = cur ^ 1;
            ((ull*)buf[nxt][r])[lane] = packf2(uA, uB);
            __syncwarp();
            cur = nxt;
        }
        // mask==0: alpha carried (buf[cur], u, s unchanged)
    }

    // logZ = s + ln(sum_j u_j); out = logZ - gold
    float tot = uA + uB;
    #pragma unroll
    for (int o = 16; o; o >>= 1) tot += __shfl_xor_sync(0xffffffffu, tot, o);
    if (lane == 0) out[b] = s + __logf(tot) - gacc;
}

extern "C" void kernel_launch(void* const* d_in, const int* in_sizes, int n_in,
                              void* d_out, int out_size)
{
    const float* logits = (const float*)d_in[0];
    const int*   tags   = (const int*)d_in[1];
    const int*   mask   = (const int*)d_in[2];
    const float* trans  = (const float*)d_in[3];
    float*       out    = (float*)d_out;

    crf_kernel<<<148, 224>>>(logits, tags, mask, trans, out);
}